// round 14
// baseline (speedup 1.0000x reference)
#include <cuda_runtime.h>
#include <cuda_fp16.h>
#include <cstdint>

#define LEVELS 18
#define NNODES ((1 << LEVELS) - 1)

// Persisted state + preconverted weights (device globals; no runtime alloc).
__device__ float  g_c [(size_t)NNODES * 64];   // cell state, cols 0..63 only
__device__ __half g_hh[(size_t)NNODES * 64];   // h fp16, cols 0..63
__device__ __half g_W [512 * 192];             // [gate][k] concat(Wih,Whh) fp16
__device__ float  g_bsum[512];
__device__ unsigned g_bar  = 0;                // grid barrier counter
__device__ unsigned g_done = 0;                // exit counter (resets g_bar)

// ------------------------------------------------------------------ helpers
__device__ __forceinline__ uint32_t smem_u32(const void* p) {
    uint32_t a;
    asm("{ .reg .u64 t; cvta.to.shared.u64 t, %1; cvt.u32.u64 %0, t; }"
        : "=r"(a) : "l"(p));
    return a;
}
__device__ __forceinline__ void ldsm_x4(uint32_t* r, uint32_t addr) {
    asm volatile("ldmatrix.sync.aligned.m8n8.x4.shared.b16 {%0,%1,%2,%3}, [%4];"
                 : "=r"(r[0]), "=r"(r[1]), "=r"(r[2]), "=r"(r[3]) : "r"(addr));
}
__device__ __forceinline__ void mma_f16(float* d, const uint32_t* a, const uint32_t* b) {
    asm volatile("mma.sync.aligned.m16n8k16.row.col.f32.f16.f16.f32 "
                 "{%0,%1,%2,%3}, {%4,%5,%6,%7}, {%8,%9}, {%0,%1,%2,%3};"
                 : "+f"(d[0]), "+f"(d[1]), "+f"(d[2]), "+f"(d[3])
                 : "r"(a[0]), "r"(a[1]), "r"(a[2]), "r"(a[3]), "r"(b[0]), "r"(b[1]));
}
__device__ __forceinline__ void cp_async16(uint32_t saddr, const void* g) {
    asm volatile("cp.async.ca.shared.global [%0], [%1], 16;"
                 :: "r"(saddr), "l"(g) : "memory");
}
__device__ __forceinline__ void cp_async_commit() {
    asm volatile("cp.async.commit_group;" ::: "memory");
}
__device__ __forceinline__ float tanhfast(float z) {
    float r;
    asm("tanh.approx.f32 %0, %1;" : "=f"(r) : "f"(z));
    return r;
}
__device__ __forceinline__ float sigf(float z) {
    return fmaf(tanhfast(0.5f * z), 0.5f, 0.5f);
}

// Software grid barrier: all nb blocks co-resident (guaranteed by launch
// config), release-fence -> arrive -> spin -> acquire-fence.
__device__ __forceinline__ void grid_barrier(unsigned target) {
    __threadfence();                       // release my prior stores
    __syncthreads();
    if (threadIdx.x == 0) {
        atomicAdd(&g_bar, 1u);
        while (*(volatile unsigned*)&g_bar < target)
            __nanosleep(100);
    }
    __syncthreads();
    __threadfence();                       // order subsequent loads
}

// ---------------------------------------------------------------- SMEM plan
// Row stride 400B: rows hit distinct bank quads -> conflict-free ldmatrix.
#define RS 400
#define OFF_BIAS 0
#define OFF_A    2048
#define OFF_B    (OFF_A + 128 * RS)     // 53248; two buffers of 25600
#define BUF_SZ   25600
#define SMEM_TC  (OFF_B + 2 * BUF_SZ)   // 104448 -> 2 CTAs/SM guaranteed
// small-path overlay (inside the OFF_A region; bias region untouched)
#define OFF_AS   2048                    // float As[8][196]
#define OFF_CS   (OFF_AS + 8 * 196 * 4)  // float Cs[8][128]

// =====================================================================
// ONE persistent kernel: prep + all 18 levels, grid barriers between.
// tc path (count >= 1024): R13 tile body in a v-strided loop.
// small path (count < 1024): R13 small body (fp32 weights) in a v loop.
// =====================================================================
__global__ __launch_bounds__(256, 2)
void lstm_persist_kernel(const float* __restrict__ x,
                         const float* __restrict__ Wih,
                         const float* __restrict__ Whh,
                         const float* __restrict__ bih,
                         const float* __restrict__ bhh,
                         float* __restrict__ out,
                         int nb)
{
    extern __shared__ __align__(16) char smem[];
    const uint32_t sb = smem_u32(smem);
    const int tid = threadIdx.x;
    const int lane = tid & 31;
    const int rg = (tid >> 5) & 3;     // row group (32 nodes)
    const int ch = tid >> 7;           // chunk half (j-tiles 4ch..4ch+3)

    // ---- prep: fp16 weights + bias sum (partitioned across grid) ----
    {
        int idx = blockIdx.x * 256 + tid;
        int stride = nb * 256;
        if (idx < 512) g_bsum[idx] = bih[idx] + bhh[idx];
        for (int p = idx; p < 512 * 192; p += stride) {
            int g = p / 192, k = p - g * 192;
            float v = (k < 64) ? Wih[g * 64 + k] : Whh[g * 128 + (k - 64)];
            g_W[p] = __float2half_rn(v);
        }
    }
    unsigned barnum = 0;
    grid_barrier(++barnum * (unsigned)nb);

    float* bs = (float*)(smem + OFF_BIAS);
    for (int i = tid; i < 512; i += 256) bs[i] = g_bsum[i];
    __syncthreads();

    for (int lvl = LEVELS - 1; lvl >= 0; --lvl) {
        const int start = (1 << lvl) - 1;
        const int count = 1 << lvl;
        const int isLeaf = (lvl == LEVELS - 1);

        if (count >= 1024) {
            // ================= tensor-core path =================
            const int tiles = count >> 7;
            int gs = 1;
            while (gs < 8 && tiles * (gs << 1) <= nb) gs <<= 1;
            const int cpc = 8 / gs;
            const int vcount = tiles * gs;

            for (int v = blockIdx.x; v < vcount; v += nb) {
                const int tile = v % tiles;
                const int nc0  = (v / tiles) * cpc;
                const int tileBase = tile * 128;
                __syncthreads();   // smem (A/B) safe to overwrite

                // ---- A assembly: [128 rows][192 k] fp16 ----
                #pragma unroll
                for (int it = 0; it < 16; ++it) {          // x: k 0..63
                    int p = tid + it * 256;
                    int row = p >> 5;
                    int kp  = (p & 31) * 2;
                    int gnode = start + tileBase + row;
                    float2 xv = *(const float2*)(x + (size_t)gnode * 64 + kp);
                    __half2 hp = {__float2half_rn(xv.x), __float2half_rn(xv.y)};
                    *(uint32_t*)(smem + OFF_A + row * RS + kp * 2) = *(uint32_t*)&hp;
                }
                if (!isLeaf) {                              // h: k 64..191
                    #pragma unroll
                    for (int it = 0; it < 8; ++it) {
                        int p = tid + it * 256;
                        int row = p >> 4;
                        int u   = p & 15;
                        int gnode = start + tileBase + row;
                        int child = (u < 8) ? (2 * gnode + 1) : (2 * gnode + 2);
                        int uu = u & 7;
                        cp_async16(sb + OFF_A + (uint32_t)(row * RS + 128 + u * 16),
                                   g_hh + (size_t)child * 64 + uu * 8);
                    }
                }

                auto issue_b = [&](int nc, int buf) {
                    uint32_t bo = sb + OFF_B + (uint32_t)buf * BUF_SZ;
                    if (isLeaf) {
                        #pragma unroll
                        for (int it = 0; it < 2; ++it) {
                            int p = tid + it * 256;        // 64 rows x 8 uint4
                            int rr = p >> 3, u = p & 7;
                            int j = rr >> 3, w = rr & 7;
                            int gate = ((j & 3) << 7) + (nc << 4) + ((j >> 2) << 3) + w;
                            cp_async16(bo + (uint32_t)(rr * RS + u * 16),
                                       g_W + (size_t)gate * 192 + u * 8);
                        }
                    } else {
                        #pragma unroll
                        for (int it = 0; it < 6; ++it) {
                            int p = tid + it * 256;        // 64 rows x 24 uint4
                            int rr = p / 24, u = p - rr * 24;
                            int j = rr >> 3, w = rr & 7;
                            int gate = ((j & 3) << 7) + (nc << 4) + ((j >> 2) << 3) + w;
                            cp_async16(bo + (uint32_t)(rr * RS + u * 16),
                                       g_W + (size_t)gate * 192 + u * 8);
                        }
                    }
                };

                issue_b(nc0, 0);
                cp_async_commit();

                const uint32_t aBase = sb + OFF_A +
                    (uint32_t)((rg * 32 + (lane & 15)) * RS + ((lane >> 4) << 4));
                const uint32_t bBase = sb + OFF_B +
                    (uint32_t)(ch * 32 * RS + (lane & 7) * RS + ((lane >> 3) << 4));
                const int r0   = rg * 32 + (lane >> 2);
                const int huL0 = (lane & 3) * 2;

                for (int l = 0; l < cpc; ++l) {
                    const int nc = nc0 + l;
                    asm volatile("cp.async.wait_group 0;" ::: "memory");
                    __syncthreads();
                    if (l + 1 < cpc) {
                        issue_b(nc + 1, (l + 1) & 1);
                        cp_async_commit();
                    }

                    const uint32_t bHi = bBase + (uint32_t)(l & 1) * BUF_SZ;
                    const int hu = (nc << 4) + (ch << 3) + huL0;

                    // c_prev prefetch: LDGs fly under the MMA chain
                    float2 cpv[2][2];
                    #pragma unroll
                    for (int m = 0; m < 2; ++m)
                        #pragma unroll
                        for (int rh = 0; rh < 2; ++rh) {
                            cpv[m][rh] = make_float2(0.f, 0.f);
                            if (!isLeaf) {
                                int row = r0 + m * 16 + 8 * rh;
                                int gnode = start + tileBase + row;
                                int child = (hu < 64) ? (2 * gnode + 1) : (2 * gnode + 2);
                                cpv[m][rh] = *(const float2*)(g_c + (size_t)child * 64 + (hu & 63));
                            }
                        }

                    float acc[2][4][4];
                    #pragma unroll
                    for (int m = 0; m < 2; ++m)
                        #pragma unroll
                        for (int j = 0; j < 4; ++j)
                            #pragma unroll
                            for (int c = 0; c < 4; ++c) acc[m][j][c] = 0.f;

                    auto do_dk = [&](int dk) {
                        uint32_t a0[2][4], a1[2][4];
                        #pragma unroll
                        for (int m = 0; m < 2; ++m) {
                            ldsm_x4(a0[m], aBase + m * (16 * RS) + dk * 64);
                            ldsm_x4(a1[m], aBase + m * (16 * RS) + dk * 64 + 32);
                        }
                        #pragma unroll
                        for (int jj = 0; jj < 4; ++jj) {
                            uint32_t bh[4];
                            ldsm_x4(bh, bHi + jj * (8 * RS) + dk * 64);
                            #pragma unroll
                            for (int m = 0; m < 2; ++m) {
                                mma_f16(acc[m][jj], a0[m], bh);
                                mma_f16(acc[m][jj], a1[m], bh + 2);
                            }
                        }
                    };
                    if (isLeaf) {
                        #pragma unroll
                        for (int dk = 0; dk < 2; ++dk) do_dk(dk);
                    } else {
                        #pragma unroll
                        for (int dk = 0; dk < 6; ++dk) do_dk(dk);
                    }

                    // fused LSTM epilogue
                    #pragma unroll
                    for (int m = 0; m < 2; ++m) {
                        #pragma unroll
                        for (int rh = 0; rh < 2; ++rh) {
                            const int row = r0 + m * 16 + 8 * rh;
                            const int gnode = start + tileBase + row;
                            float2 cp = cpv[m][rh];
                            float gi0 = acc[m][0][2 * rh]     + bs[hu];
                            float gi1 = acc[m][0][2 * rh + 1] + bs[hu + 1];
                            float gf0 = acc[m][1][2 * rh]     + bs[128 + hu];
                            float gf1 = acc[m][1][2 * rh + 1] + bs[128 + hu + 1];
                            float gg0 = acc[m][2][2 * rh]     + bs[256 + hu];
                            float gg1 = acc[m][2][2 * rh + 1] + bs[256 + hu + 1];
                            float go0 = acc[m][3][2 * rh]     + bs[384 + hu];
                            float go1 = acc[m][3][2 * rh + 1] + bs[384 + hu + 1];
                            float c0 = sigf(gf0) * cp.x + sigf(gi0) * tanhfast(gg0);
                            float c1 = sigf(gf1) * cp.y + sigf(gi1) * tanhfast(gg1);
                            float h0 = sigf(go0) * tanhfast(c0);
                            float h1 = sigf(go1) * tanhfast(c1);
                            *(float2*)(out + (size_t)gnode * 128 + hu) = make_float2(h0, h1);
                            if (hu < 64) {
                                *(float2*)(g_c + (size_t)gnode * 64 + hu) = make_float2(c0, c1);
                                __half2 hp = {__float2half_rn(h0), __float2half_rn(h1)};
                                *(uint32_t*)(g_hh + (size_t)gnode * 64 + hu) = *(uint32_t*)&hp;
                            }
                        }
                    }
                }
            }
        } else {
            // ================= small SIMT path (count <= 512) =================
            float* As = (float*)(smem + OFF_AS);   // [8][196]
            float* Cs = (float*)(smem + OFF_CS);   // [8][128]
            const int tiles8 = (count + 7) >> 3;

            for (int v = blockIdx.x; v < tiles8; v += nb) {
                const int tileBase = v * 8;
                __syncthreads();

                for (int q = tid; q < 384; q += 256) {
                    int node = q / 48, c4 = q - node * 48, col = c4 * 4;
                    float4 vv = make_float4(0.f, 0.f, 0.f, 0.f);
                    int nodeIdx = tileBase + node;
                    if (nodeIdx < count) {
                        int gnode = start + nodeIdx;
                        if (col < 64) {
                            vv = *(const float4*)(x + (size_t)gnode * 64 + col);
                        } else {
                            int child = (col < 128) ? (2 * gnode + 1) : (2 * gnode + 2);
                            int cc    = (col < 128) ? (col - 64) : (col - 128);
                            vv = *(const float4*)(out + (size_t)child * 128 + cc);
                        }
                    }
                    *(float4*)&As[node * 196 + col] = vv;
                }
                {
                    int node = tid / 32, col = (tid & 31) * 4;
                    float4 vv = make_float4(0.f, 0.f, 0.f, 0.f);
                    int nodeIdx = tileBase + node;
                    if (nodeIdx < count) {
                        int gnode = start + nodeIdx;
                        int child = (col < 64) ? (2 * gnode + 1) : (2 * gnode + 2);
                        int cc    = (col < 64) ? col : (col - 64);
                        vv = *(const float4*)&g_c[(size_t)child * 64 + cc];
                    }
                    *(float4*)&Cs[node * 128 + col] = vv;
                }
                __syncthreads();

                const int hu = tid & 127;
                const int np = tid >> 7;
                float acc[4][4];
                #pragma unroll
                for (int n = 0; n < 4; ++n)
                    #pragma unroll
                    for (int g = 0; g < 4; ++g)
                        acc[n][g] = bs[hu + g * 128];

                for (int kc = 0; kc < 48; ++kc) {
                    const int k0 = kc * 4;
                    float4 w[4];
                    #pragma unroll
                    for (int g = 0; g < 4; ++g) {
                        int grow = hu + g * 128;
                        w[g] = (k0 < 64)
                             ? *(const float4*)(Wih + (size_t)grow * 64 + k0)
                             : *(const float4*)(Whh + (size_t)grow * 128 + (k0 - 64));
                    }
                    #pragma unroll
                    for (int n = 0; n < 4; ++n) {
                        float4 a = *(const float4*)&As[(np + 2 * n) * 196 + k0];
                        #pragma unroll
                        for (int g = 0; g < 4; ++g)
                            acc[n][g] += a.x * w[g].x + a.y * w[g].y
                                       + a.z * w[g].z + a.w * w[g].w;
                    }
                }

                #pragma unroll
                for (int n = 0; n < 4; ++n) {
                    int nn = np + 2 * n;
                    int nodeIdx = tileBase + nn;
                    if (nodeIdx < count) {
                        int gnode = start + nodeIdx;
                        float cpv = Cs[nn * 128 + hu];
                        float c = sigf(acc[n][1]) * cpv + sigf(acc[n][0]) * tanhfast(acc[n][2]);
                        float h = sigf(acc[n][3]) * tanhfast(c);
                        out[(size_t)gnode * 128 + hu] = h;
                        if (hu < 64) g_c[(size_t)gnode * 64 + hu] = c;
                    }
                }
            }
        }

        if (lvl > 0) grid_barrier(++barnum * (unsigned)nb);
    }

    // ---- exit: last block resets barrier counters for the next replay ----
    __syncthreads();
    if (tid == 0) {
        __threadfence();
        unsigned d = atomicAdd(&g_done, 1u) + 1u;
        if (d == (unsigned)nb) {
            *(volatile unsigned*)&g_bar  = 0u;
            *(volatile unsigned*)&g_done = 0u;
            __threadfence();
        }
    }
}

extern "C" void kernel_launch(void* const* d_in, const int* in_sizes, int n_in,
                              void* d_out, int out_size)
{
    const float* x   = (const float*)d_in[0];   // [262143, 64]
    const float* Wih = (const float*)d_in[1];   // [512, 64]
    const float* Whh = (const float*)d_in[2];   // [512, 128]
    const float* bih = (const float*)d_in[3];   // [512]
    const float* bhh = (const float*)d_in[4];   // [512]
    float* out = (float*)d_out;                 // [262143, 128]

    static int nb = 0;
    if (nb == 0) {                  // first (uncaptured) call only
        int smc = 0;
        cudaDeviceGetAttribute(&smc, cudaDevAttrMultiProcessorCount, 0);
        nb = smc * 2;               // 2 CTAs/SM, all co-resident
        cudaFuncSetAttribute(lstm_persist_kernel,
                             cudaFuncAttributeMaxDynamicSharedMemorySize, SMEM_TC);
    }

    lstm_persist_kernel<<<nb, 256, SMEM_TC>>>(x, Wih, Whh, bih, bhh, out, nb);
}

// round 15
// speedup vs baseline: 1.5447x; 1.5447x over previous
#include <cuda_runtime.h>
#include <cuda_fp16.h>
#include <cstdint>

#define LEVELS 18
#define NNODES ((1 << LEVELS) - 1)

// Persisted state + preconverted weights (device globals; no runtime alloc).
__device__ float  g_c [(size_t)NNODES * 64];   // cell state, cols 0..63 only
__device__ __half g_hh[(size_t)NNODES * 64];   // h fp16, cols 0..63
__device__ __half g_W [512 * 192];             // [gate][k] concat(Wih,Whh) fp16
__device__ float  g_bsum[512];
__device__ unsigned g_tbar  = 0;               // tail-kernel barrier counter
__device__ unsigned g_tdone = 0;               // tail-kernel exit counter

// ------------------------------------------------------------------ helpers
__device__ __forceinline__ uint32_t smem_u32(const void* p) {
    uint32_t a;
    asm("{ .reg .u64 t; cvta.to.shared.u64 t, %1; cvt.u32.u64 %0, t; }"
        : "=r"(a) : "l"(p));
    return a;
}
__device__ __forceinline__ void ldsm_x4(uint32_t* r, uint32_t addr) {
    asm volatile("ldmatrix.sync.aligned.m8n8.x4.shared.b16 {%0,%1,%2,%3}, [%4];"
                 : "=r"(r[0]), "=r"(r[1]), "=r"(r[2]), "=r"(r[3]) : "r"(addr));
}
__device__ __forceinline__ void mma_f16(float* d, const uint32_t* a, const uint32_t* b) {
    asm volatile("mma.sync.aligned.m16n8k16.row.col.f32.f16.f16.f32 "
                 "{%0,%1,%2,%3}, {%4,%5,%6,%7}, {%8,%9}, {%0,%1,%2,%3};"
                 : "+f"(d[0]), "+f"(d[1]), "+f"(d[2]), "+f"(d[3])
                 : "r"(a[0]), "r"(a[1]), "r"(a[2]), "r"(a[3]), "r"(b[0]), "r"(b[1]));
}
__device__ __forceinline__ void cp_async16(uint32_t saddr, const void* g) {
    asm volatile("cp.async.ca.shared.global [%0], [%1], 16;"
                 :: "r"(saddr), "l"(g) : "memory");
}
__device__ __forceinline__ void cp_async_commit() {
    asm volatile("cp.async.commit_group;" ::: "memory");
}
__device__ __forceinline__ float tanhfast(float z) {
    float r;
    asm("tanh.approx.f32 %0, %1;" : "=f"(r) : "f"(z));
    return r;
}
__device__ __forceinline__ float sigf(float z) {
    return fmaf(tanhfast(0.5f * z), 0.5f, 0.5f);
}

// ---------------------------------------------------------------- SMEM plan
// Row stride 400B: rows hit distinct bank quads -> conflict-free ldmatrix.
#define RS 400
#define OFF_BIAS 0
#define OFF_A    2048
#define OFF_B    (OFF_A + 128 * RS)     // 53248; two buffers of 25600
#define BUF_SZ   25600
#define SMEM_TC  (OFF_B + 2 * BUF_SZ)   // 104448 -> 2 CTAs/SM (16 warps/SM)

// ---------------------------------------------------------------- prep
__global__ void prep_kernel(const float* __restrict__ Wih,
                            const float* __restrict__ Whh,
                            const float* __restrict__ bih,
                            const float* __restrict__ bhh)
{
    int idx = blockIdx.x * blockDim.x + threadIdx.x;
    if (idx < 512) g_bsum[idx] = bih[idx] + bhh[idx];
    for (int p = idx; p < 512 * 192; p += gridDim.x * blockDim.x) {
        int g = p / 192, k = p - g * 192;
        float v = (k < 64) ? Wih[g * 64 + k] : Whh[g * 128 + (k - 64)];
        g_W[p] = __float2half_rn(v);
    }
}

// =====================================================================
// Tensor-core level kernel (UNCHANGED from R13 best): CTA = 128 nodes x
// (512/gs) gates, 256 threads, 8 warps, 2 CTAs/SM. Single-term fp16.
// =====================================================================
__global__ __launch_bounds__(256, 2)
void lstm_tc_kernel(const float* __restrict__ x,
                    float* __restrict__ out,
                    int start, int isLeaf, int tiles, int cpc)
{
    extern __shared__ __align__(16) char smem[];
    const uint32_t sb = smem_u32(smem);
    const int tid = threadIdx.x;
    const int lane = tid & 31;
    const int rg = (tid >> 5) & 3;     // row group (32 nodes)
    const int ch = tid >> 7;           // chunk half (j-tiles 4ch..4ch+3)
    const int tile  = blockIdx.x % tiles;
    const int nc0   = (blockIdx.x / tiles) * cpc;   // first gate-chunk
    const int tileBase = tile * 128;

    float* bs = (float*)(smem + OFF_BIAS);
    for (int i = tid; i < 512; i += 256) bs[i] = g_bsum[i];

    // ---- A assembly: [128 rows][192 k] fp16 ----
    #pragma unroll
    for (int it = 0; it < 16; ++it) {              // x part: k 0..63 (convert)
        int p = tid + it * 256;
        int row = p >> 5;
        int kp  = (p & 31) * 2;
        int gnode = start + tileBase + row;
        float2 xv = *(const float2*)(x + (size_t)gnode * 64 + kp);
        __half2 hp = {__float2half_rn(xv.x), __float2half_rn(xv.y)};
        *(uint32_t*)(smem + OFF_A + row * RS + kp * 2) = *(uint32_t*)&hp;
    }
    if (!isLeaf) {                                  // h part: k 64..191, cp.async
        #pragma unroll
        for (int it = 0; it < 8; ++it) {
            int p = tid + it * 256;
            int row = p >> 4;
            int u   = p & 15;                       // 0..7 left, 8..15 right
            int gnode = start + tileBase + row;
            int child = (u < 8) ? (2 * gnode + 1) : (2 * gnode + 2);
            int uu = u & 7;
            cp_async16(sb + OFF_A + (uint32_t)(row * RS + 128 + u * 16),
                       g_hh + (size_t)child * 64 + uu * 8);
        }
    }

    auto issue_b = [&](int nc, int buf) {
        uint32_t bo = sb + OFF_B + (uint32_t)buf * BUF_SZ;
        if (isLeaf) {
            #pragma unroll
            for (int it = 0; it < 2; ++it) {
                int p = tid + it * 256;            // p < 512: 64 rows x 8 uint4
                int rr = p >> 3, u = p & 7;
                int j = rr >> 3, w = rr & 7;
                int gate = ((j & 3) << 7) + (nc << 4) + ((j >> 2) << 3) + w;
                cp_async16(bo + (uint32_t)(rr * RS + u * 16),
                           g_W + (size_t)gate * 192 + u * 8);
            }
        } else {
            #pragma unroll
            for (int it = 0; it < 6; ++it) {
                int p = tid + it * 256;            // p < 1536: 64 rows x 24
                int rr = p / 24, u = p - rr * 24;
                int j = rr >> 3, w = rr & 7;
                int gate = ((j & 3) << 7) + (nc << 4) + ((j >> 2) << 3) + w;
                cp_async16(bo + (uint32_t)(rr * RS + u * 16),
                           g_W + (size_t)gate * 192 + u * 8);
            }
        }
    };

    issue_b(nc0, 0);        // group 0 = A h-parts + B chunk nc0
    cp_async_commit();

    const uint32_t aBase = sb + OFF_A +
        (uint32_t)((rg * 32 + (lane & 15)) * RS + ((lane >> 4) << 4));
    const uint32_t bBase = sb + OFF_B +
        (uint32_t)(ch * 32 * RS + (lane & 7) * RS + ((lane >> 3) << 4));
    const int r0   = rg * 32 + (lane >> 2);
    const int huL0 = (lane & 3) * 2;

    for (int l = 0; l < cpc; ++l) {
        const int nc = nc0 + l;
        asm volatile("cp.async.wait_group 0;" ::: "memory");
        __syncthreads();
        if (l + 1 < cpc) {
            issue_b(nc + 1, (l + 1) & 1);
            cp_async_commit();
        }

        const uint32_t bHi = bBase + (uint32_t)(l & 1) * BUF_SZ;
        const int hu = (nc << 4) + (ch << 3) + huL0;

        // ---- c_prev prefetch: LDGs fly under the MMA chain below ----
        float2 cpv[2][2];
        #pragma unroll
        for (int m = 0; m < 2; ++m)
            #pragma unroll
            for (int rh = 0; rh < 2; ++rh) {
                cpv[m][rh] = make_float2(0.f, 0.f);
                if (!isLeaf) {
                    int row = r0 + m * 16 + 8 * rh;
                    int gnode = start + tileBase + row;
                    int child = (hu < 64) ? (2 * gnode + 1) : (2 * gnode + 2);
                    cpv[m][rh] = *(const float2*)(g_c + (size_t)child * 64 + (hu & 63));
                }
            }

        float acc[2][4][4];
        #pragma unroll
        for (int m = 0; m < 2; ++m)
            #pragma unroll
            for (int j = 0; j < 4; ++j)
                #pragma unroll
                for (int c = 0; c < 4; ++c) acc[m][j][c] = 0.f;

        auto do_dk = [&](int dk) {
            uint32_t a0[2][4], a1[2][4];
            #pragma unroll
            for (int m = 0; m < 2; ++m) {
                ldsm_x4(a0[m], aBase + m * (16 * RS) + dk * 64);
                ldsm_x4(a1[m], aBase + m * (16 * RS) + dk * 64 + 32);
            }
            #pragma unroll
            for (int jj = 0; jj < 4; ++jj) {
                uint32_t bh[4];
                ldsm_x4(bh, bHi + jj * (8 * RS) + dk * 64);
                #pragma unroll
                for (int m = 0; m < 2; ++m) {
                    mma_f16(acc[m][jj], a0[m], bh);
                    mma_f16(acc[m][jj], a1[m], bh + 2);
                }
            }
        };
        if (isLeaf) {
            #pragma unroll
            for (int dk = 0; dk < 2; ++dk) do_dk(dk);   // x columns only
        } else {
            #pragma unroll
            for (int dk = 0; dk < 6; ++dk) do_dk(dk);
        }

        // ---- fused LSTM epilogue: this warp owns full (i,f,g,o) quad ----
        #pragma unroll
        for (int m = 0; m < 2; ++m) {
            #pragma unroll
            for (int rh = 0; rh < 2; ++rh) {
                const int row = r0 + m * 16 + 8 * rh;
                const int gnode = start + tileBase + row;
                float2 cp = cpv[m][rh];
                float gi0 = acc[m][0][2 * rh]     + bs[hu];
                float gi1 = acc[m][0][2 * rh + 1] + bs[hu + 1];
                float gf0 = acc[m][1][2 * rh]     + bs[128 + hu];
                float gf1 = acc[m][1][2 * rh + 1] + bs[128 + hu + 1];
                float gg0 = acc[m][2][2 * rh]     + bs[256 + hu];
                float gg1 = acc[m][2][2 * rh + 1] + bs[256 + hu + 1];
                float go0 = acc[m][3][2 * rh]     + bs[384 + hu];
                float go1 = acc[m][3][2 * rh + 1] + bs[384 + hu + 1];
                float c0 = sigf(gf0) * cp.x + sigf(gi0) * tanhfast(gg0);
                float c1 = sigf(gf1) * cp.y + sigf(gi1) * tanhfast(gg1);
                float h0 = sigf(go0) * tanhfast(c0);
                float h1 = sigf(go1) * tanhfast(c1);
                *(float2*)(out + (size_t)gnode * 128 + hu) = make_float2(h0, h1);
                if (hu < 64) {
                    *(float2*)(g_c + (size_t)gnode * 64 + hu) = make_float2(c0, c1);
                    __half2 hp = {__float2half_rn(h0), __float2half_rn(h1)};
                    *(uint32_t*)(g_hh + (size_t)gnode * 64 + hu) = *(uint32_t*)&hp;
                }
            }
        }
    }
}

// =====================================================================
// Fused TAIL kernel: levels 9..0 (count 512..1) in ONE launch.
// 64 blocks x 256 threads, single wave, internal counter barrier.
// count >= 64 -> 8-node SIMT tile body; count < 64 -> 1-node tiny body.
// =====================================================================
#define TAIL_NB 64

__global__ __launch_bounds__(256, 2)
void lstm_tail_kernel(const float* __restrict__ x,
                      const float* __restrict__ Wih,
                      const float* __restrict__ Whh,
                      const float* __restrict__ bih,
                      const float* __restrict__ bhh,
                      float* __restrict__ out)
{
    __shared__ __align__(16) float As[8][196];
    __shared__ __align__(16) float Cs[8][128];
    __shared__ float bsm[512];
    __shared__ float Atn[192];     // tiny-path A
    __shared__ float Cpt[128];     // tiny-path c_prev
    __shared__ float gts[512];     // tiny-path gates

    const int t = threadIdx.x;
    for (int i = t; i < 512; i += 256) bsm[i] = bih[i] + bhh[i];
    __syncthreads();

    unsigned barnum = 0;

    for (int lvl = 9; lvl >= 0; --lvl) {
        const int start = (1 << lvl) - 1;
        const int count = 1 << lvl;

        if (count >= 64) {
            // ---- 8-node tile body; tiles = count/8 <= 64 = one per block ----
            const int tiles8 = count >> 3;
            if ((int)blockIdx.x < tiles8) {
                const int tileBase = blockIdx.x * 8;

                for (int q = t; q < 384; q += 256) {
                    int node = q / 48, c4 = q - node * 48, col = c4 * 4;
                    int gnode = start + tileBase + node;
                    float4 v;
                    if (col < 64) {
                        v = *(const float4*)(x + (size_t)gnode * 64 + col);
                    } else {
                        int child = (col < 128) ? (2 * gnode + 1) : (2 * gnode + 2);
                        int cc    = (col < 128) ? (col - 64) : (col - 128);
                        v = *(const float4*)(out + (size_t)child * 128 + cc);
                    }
                    *(float4*)&As[node][col] = v;
                }
                {
                    int node = t / 32, col = (t & 31) * 4;
                    int gnode = start + tileBase + node;
                    int child = (col < 64) ? (2 * gnode + 1) : (2 * gnode + 2);
                    int cc    = (col < 64) ? col : (col - 64);
                    *(float4*)&Cs[node][col] =
                        *(const float4*)&g_c[(size_t)child * 64 + cc];
                }
                __syncthreads();

                const int hu = t & 127;
                const int np = t >> 7;
                float acc[4][4];
                #pragma unroll
                for (int n = 0; n < 4; ++n)
                    #pragma unroll
                    for (int g = 0; g < 4; ++g)
                        acc[n][g] = bsm[hu + g * 128];

                for (int kc = 0; kc < 48; ++kc) {
                    const int k0 = kc * 4;
                    float4 w[4];
                    #pragma unroll
                    for (int g = 0; g < 4; ++g) {
                        int grow = hu + g * 128;
                        w[g] = (k0 < 64)
                             ? *(const float4*)(Wih + (size_t)grow * 64 + k0)
                             : *(const float4*)(Whh + (size_t)grow * 128 + (k0 - 64));
                    }
                    #pragma unroll
                    for (int n = 0; n < 4; ++n) {
                        float4 a = *(const float4*)&As[np + 2 * n][k0];
                        #pragma unroll
                        for (int g = 0; g < 4; ++g)
                            acc[n][g] += a.x * w[g].x + a.y * w[g].y
                                       + a.z * w[g].z + a.w * w[g].w;
                    }
                }

                #pragma unroll
                for (int n = 0; n < 4; ++n) {
                    int nn = np + 2 * n;
                    int gnode = start + tileBase + nn;
                    float cp = Cs[nn][hu];
                    float c = sigf(acc[n][1]) * cp + sigf(acc[n][0]) * tanhfast(acc[n][2]);
                    float h = sigf(acc[n][3]) * tanhfast(c);
                    out[(size_t)gnode * 128 + hu] = h;
                    if (hu < 64) g_c[(size_t)gnode * 64 + hu] = c;
                }
                __syncthreads();
            }
        } else {
            // ---- tiny body: block b handles node b (b < count) ----
            if ((int)blockIdx.x < count) {
                const int gnode = start + blockIdx.x;
                if (t < 192) {
                    if (t < 64) {
                        Atn[t] = x[(size_t)gnode * 64 + t];
                    } else {
                        int k = t - 64;
                        int child = (k < 64) ? (2 * gnode + 1) : (2 * gnode + 2);
                        Atn[t] = out[(size_t)child * 128 + (k & 63)];
                    }
                }
                if (t < 128) {
                    int child = (t < 64) ? (2 * gnode + 1) : (2 * gnode + 2);
                    Cpt[t] = g_c[(size_t)child * 64 + (t & 63)];
                }
                __syncthreads();

                #pragma unroll
                for (int gg = 0; gg < 2; ++gg) {
                    int g = t + gg * 256;
                    float acc = bsm[g];
                    const float* wx = Wih + (size_t)g * 64;
                    const float* wh = Whh + (size_t)g * 128;
                    #pragma unroll
                    for (int k = 0; k < 64; k += 4) {
                        float4 w = *(const float4*)(wx + k);
                        acc += w.x * Atn[k] + w.y * Atn[k+1] + w.z * Atn[k+2] + w.w * Atn[k+3];
                    }
                    #pragma unroll
                    for (int k = 0; k < 128; k += 4) {
                        float4 w = *(const float4*)(wh + k);
                        acc += w.x * Atn[64+k] + w.y * Atn[65+k] + w.z * Atn[66+k] + w.w * Atn[67+k];
                    }
                    gts[g] = acc;
                }
                __syncthreads();

                if (t < 128) {
                    float c = sigf(gts[128 + t]) * Cpt[t] + sigf(gts[t]) * tanhfast(gts[256 + t]);
                    float h = sigf(gts[384 + t]) * tanhfast(c);
                    out[(size_t)gnode * 128 + t] = h;
                    if (t < 64) g_c[(size_t)gnode * 64 + t] = c;
                }
                __syncthreads();
            }
        }

        // ---- barrier between levels (skip after the root) ----
        if (lvl > 0) {
            __threadfence();
            __syncthreads();
            if (t == 0) {
                ++barnum;
                atomicAdd(&g_tbar, 1u);
                unsigned target = barnum * (unsigned)TAIL_NB;
                while (*(volatile unsigned*)&g_tbar < target)
                    __nanosleep(60);
            }
            __syncthreads();
            __threadfence();
        }
    }

    // ---- exit: last block resets counters for the next graph replay ----
    __syncthreads();
    if (t == 0) {
        __threadfence();
        unsigned d = atomicAdd(&g_tdone, 1u) + 1u;
        if (d == (unsigned)TAIL_NB) {
            *(volatile unsigned*)&g_tbar  = 0u;
            *(volatile unsigned*)&g_tdone = 0u;
            __threadfence();
        }
    }
}

extern "C" void kernel_launch(void* const* d_in, const int* in_sizes, int n_in,
                              void* d_out, int out_size)
{
    const float* x   = (const float*)d_in[0];   // [262143, 64]
    const float* Wih = (const float*)d_in[1];   // [512, 64]
    const float* Whh = (const float*)d_in[2];   // [512, 128]
    const float* bih = (const float*)d_in[3];   // [512]
    const float* bhh = (const float*)d_in[4];   // [512]
    float* out = (float*)d_out;                 // [262143, 128]

    static bool attr_done = false;
    if (!attr_done) {
        cudaFuncSetAttribute(lstm_tc_kernel,
                             cudaFuncAttributeMaxDynamicSharedMemorySize, SMEM_TC);
        attr_done = true;
    }

    prep_kernel<<<96, 256>>>(Wih, Whh, bih, bhh);

    const int CONC = 296;   // 148 SMs x 2 CTAs
    for (int lvl = LEVELS - 1; lvl >= 10; --lvl) {
        int start = (1 << lvl) - 1;
        int count = 1 << lvl;
        int isLeaf = (lvl == LEVELS - 1);
        int tiles = count / 128;
        int gs = 1;
        while (gs < 8 && tiles * gs * 2 <= CONC) gs <<= 1;  // fill, 1 wave
        lstm_tc_kernel<<<tiles * gs, 256, SMEM_TC>>>(
            x, out, start, isLeaf, tiles, 8 / gs);
    }
    // levels 9..0 in one persistent launch
    lstm_tail_kernel<<<TAIL_NB, 256>>>(x, Wih, Whh, bih, bhh, out);
}